// round 16
// baseline (speedup 1.0000x reference)
#include <cuda_runtime.h>
#include <math.h>

#define B_      32
#define CIN     2048
#define NPIX    625        // 25*25
#define NANC    9
#define HID     9
#define HID2    10         // padded (h=9 zero) -> 5 f32x2 pairs
#define NPOS    2048
#define NENT    4096
#define MAXINST 256
#define CSTG    8          // channels per smem stage (1 per warp)
#define NPER    5          // instances per thread
#define WIN     160        // instances per sweep (32 lanes * 5)
#define NGRP    9          // grid.y -> 288 blocks
#define NCHUNKS (NGRP * 8) // 72 partial chunks

typedef unsigned long long ull;

// Scratch (device globals: no allocation allowed)
__device__ float d_part[(size_t)NCHUNKS * NENT * HID2];  // ~11.8 MB, write-once
__device__ ull   d_Wp[CIN * 50];   // [c][h2][10 taps] f32x2 pairs (tap 9 = pad)

__device__ __forceinline__ ull pk2(float lo, float hi) {
    ull r; asm("mov.b64 %0, {%1, %2};" : "=l"(r) : "f"(lo), "f"(hi)); return r;
}
__device__ __forceinline__ void fma2(ull& d, ull a, ull b) {
    asm("fma.rn.f32x2 %0, %1, %2, %3;" : "=l"(d) : "l"(a), "l"(b), "l"(d));
}
__device__ __forceinline__ void cpa16(unsigned s, const void* g) {
    asm volatile("cp.async.cg.shared.global [%0], [%1], 16;" :: "r"(s), "l"(g));
}
#define CPA_COMMIT() asm volatile("cp.async.commit_group;")
#define CPA_WAIT0()  asm volatile("cp.async.wait_group 0;" ::: "memory")

// dynamic smem layout (bytes)
#define FBUF      20000                     // 8 * 625 * 4
#define WBUF      3200                      // 8 * 50 * 8
#define OFF_SW    (2 * FBUF)                // 40000
#define OFF_UB    (OFF_SW + 2 * WBUF)       // 46400
#define OFF_UE    (OFF_UB + MAXINST * 2)
#define OFF_SB    (OFF_UE + MAXINST * 2)
#define OFF_SE    (OFF_SB + MAXINST * 2)
#define OFF_BCNT  (OFF_SE + MAXINST * 2)
#define OFF_BOFF  (OFF_BCNT + 128)
#define OFF_CNT   (OFF_BOFF + 128)
#define SMEM_BYTES (OFF_CNT + 16)           // ~48.7 KB -> 3 blocks/SM

// ---------------- K0: pack weights [h][c][3][3] -> [c][h2][10] f32x2 pairs
__global__ void k_prep(const float* __restrict__ Wh) {
    int idx = blockIdx.x * blockDim.x + threadIdx.x;
    if (idx >= CIN * 50) return;
    int c = idx / 50, rm = idx % 50, h2 = rm / 10, t = rm % 10;
    float lo = 0.f, hi = 0.f;
    if (t < 9) {
        lo = Wh[((size_t)(2 * h2) * CIN + c) * 9 + t];
        if (2 * h2 + 1 < HID) hi = Wh[((size_t)(2 * h2 + 1) * CIN + c) * 9 + t];
    }
    ((float2*)d_Wp)[idx] = make_float2(lo, hi);
}

// ---------------- K1: sparse 3x3 conv partials.
// grid = (32 images, 9 channel-groups); block = 256 threads (8 warps), 3 blocks/SM.
// cp.async double-buffered, 1 barrier/stage, lane=instance (residue-sorted),
// 1 channel per warp per stage, f32x2 hid-pairs, predicated border LDS.
__global__ void __launch_bounds__(256, 3) k_conv(
    const float* __restrict__ F,
    const int* __restrict__ posi,
    const int* __restrict__ negi)
{
    extern __shared__ char smem[];
    float* sF = (float*)smem;                        // 2 x 8 planes of 625
    unsigned short* s_ub = (unsigned short*)(smem + OFF_UB);
    unsigned short* s_ue = (unsigned short*)(smem + OFF_UE);
    unsigned short* s_sb = (unsigned short*)(smem + OFF_SB);
    unsigned short* s_se = (unsigned short*)(smem + OFF_SE);
    int* s_bcnt = (int*)(smem + OFF_BCNT);
    int* s_boff = (int*)(smem + OFF_BOFF);
    int* s_cnt  = (int*)(smem + OFF_CNT);
    const unsigned sm0 = (unsigned)__cvta_generic_to_shared(smem);

    const int b    = blockIdx.x;
    const int g    = blockIdx.y;
    const int c0   = (g < 5) ? g * 224 : 1120 + (g - 5) * 232;  // 5x28 + 4x29 stages
    const int nst  = (g < 5) ? 28 : 29;                          // of 8 channels
    const int tid  = threadIdx.x;
    const int lane = tid & 31;
    const int wid  = tid >> 5;

    if (tid == 0) *s_cnt = 0;
    if (tid < 32) s_bcnt[tid] = 0;
    __syncthreads();

    // gather entries of image b; key = conv base offset (y-1)*25+(x-1), stored +64
    for (int e = tid; e < NENT; e += 256) {
        int flat = (e < NPOS) ? posi[e] : negi[e - NPOS];
        if (flat / (NPIX * NANC) == b) {
            int s = atomicAdd(s_cnt, 1);
            if (s < MAXINST) {
                int rem = flat % (NPIX * NANC);
                int pix = rem / NANC;
                int y = pix / 25, x = pix - y * 25;
                s_ub[s] = (unsigned short)((y - 1) * 25 + (x - 1) + 64);
                s_ue[s] = (unsigned short)e;
            }
        }
    }
    __syncthreads();
    const int ninst = min(*s_cnt, MAXINST);
    if (ninst == 0) return;   // block-uniform; no cp.async issued yet

    // counting sort by (base mod 32) -> near-conflict-free patch LDS
    for (int i = tid; i < ninst; i += 256) atomicAdd(&s_bcnt[s_ub[i] & 31], 1);
    __syncthreads();
    if (wid == 0) {
        int v = s_bcnt[lane];
#pragma unroll
        for (int d = 1; d < 32; d <<= 1) {
            int t = __shfl_up_sync(0xffffffffu, v, d);
            if (lane >= d) v += t;
        }
        s_boff[lane] = v - s_bcnt[lane];
    }
    __syncthreads();
    for (int i = tid; i < ninst; i += 256) {
        int bs = s_ub[i];
        int p = atomicAdd(&s_boff[bs & 31], 1);
        s_sb[p] = (unsigned short)bs;
        s_se[p] = s_ue[i];
    }
    __syncthreads();

    for (int w0 = 0; w0 < ninst; w0 += WIN) {
        // per-thread instances: base + 9-bit border mask (invalid -> mk=0)
        int      ibase[NPER];
        unsigned mk[NPER];
#pragma unroll
        for (int j = 0; j < NPER; j++) {
            int r = w0 + lane * NPER + j;
            if (r < ninst) {
                int base = (int)s_sb[r] - 64;
                ibase[j] = base;
                int v = base + 26;          // = 25*y + x
                int y = v / 25, x = v - 25 * y;
                unsigned m = 0;
#pragma unroll
                for (int t = 0; t < 9; t++) {
                    int dy = t / 3, dx = t - dy * 3;
                    if ((unsigned)(y - 1 + dy) < 25u && (unsigned)(x - 1 + dx) < 25u)
                        m |= 1u << t;
                }
                mk[j] = m;
            } else { ibase[j] = 0; mk[j] = 0u; }
        }

        ull acc[NPER][5];
#pragma unroll
        for (int j = 0; j < NPER; j++)
#pragma unroll
            for (int h2 = 0; h2 < 5; h2++) acc[j][h2] = 0ull;

        // cp.async stage issue: F (1250 x 16B) + packed W (200 x 16B)
        auto stage_issue = [&](int s) {
            const int cb = c0 + s * CSTG;
            const char* gF = (const char*)(F + ((size_t)b * CIN + cb) * NPIX);
            const unsigned dF = sm0 + (s & 1) * FBUF;
            for (int i = tid; i < FBUF / 16; i += 256) cpa16(dF + i * 16, gF + i * 16);
            const char* gW = (const char*)(d_Wp + (size_t)cb * 50);
            const unsigned dW = sm0 + OFF_SW + (s & 1) * WBUF;
            for (int i = tid; i < WBUF / 16; i += 256) cpa16(dW + i * 16, gW + i * 16);
            CPA_COMMIT();
        };

        stage_issue(0);
        for (int s = 0; s < nst; s++) {
            CPA_WAIT0();          // this stage's copies done (this thread)
            __syncthreads();      // visible block-wide; prev compute done
            if (s + 1 < nst) stage_issue(s + 1);   // overlaps compute below

            const int buf = s & 1;
            const float* fpl = sF + buf * (FBUF / 4) + wid * NPIX;
            const ull*   wk  = (const ull*)(smem + OFF_SW + buf * WBUF) + wid * 50;
            // tap pairs (0,1)(2,3)(4,5)(6,7): LDS.128 weight loads
#pragma unroll
            for (int tp = 0; tp < 4; tp++) {
                const int t0 = 2 * tp, t1 = t0 + 1;
                const int o0 = (t0 / 3) * 25 + t0 % 3;
                const int o1 = (t1 / 3) * 25 + t1 % 3;
                ulonglong2 w01[5];
#pragma unroll
                for (int h2 = 0; h2 < 5; h2++)
                    w01[h2] = *(const ulonglong2*)(wk + h2 * 10 + t0);
#pragma unroll
                for (int j = 0; j < NPER; j++) {
                    float v0 = 0.f, v1 = 0.f;
                    if (mk[j] >> t0 & 1u) v0 = fpl[ibase[j] + o0];
                    if (mk[j] >> t1 & 1u) v1 = fpl[ibase[j] + o1];
                    ull p0 = pk2(v0, v0), p1 = pk2(v1, v1);
#pragma unroll
                    for (int h2 = 0; h2 < 5; h2++) {
                        fma2(acc[j][h2], p0, w01[h2].x);
                        fma2(acc[j][h2], p1, w01[h2].y);
                    }
                }
            }
            // tap 8
            {
                ull w8[5];
#pragma unroll
                for (int h2 = 0; h2 < 5; h2++) w8[h2] = wk[h2 * 10 + 8];
#pragma unroll
                for (int j = 0; j < NPER; j++) {
                    float v = 0.f;
                    if (mk[j] >> 8 & 1u) v = fpl[ibase[j] + 52];
                    ull p = pk2(v, v);
#pragma unroll
                    for (int h2 = 0; h2 < 5; h2++) fma2(acc[j][h2], p, w8[h2]);
                }
            }
        }

        // write-once partials: chunk = (g, warp)
        const int chunk = g * 8 + wid;
        float* cp = d_part + (size_t)chunk * NENT * HID2;
#pragma unroll
        for (int j = 0; j < NPER; j++) {
            int r = w0 + lane * NPER + j;
            if (r >= ninst) continue;
            int e = s_se[r];
            ull* dst = (ull*)(cp + e * HID2);
#pragma unroll
            for (int h2 = 0; h2 < 5; h2++) dst[h2] = acc[j][h2];
        }
        __syncthreads();   // (rare multi-sweep) buffers free before restage
    }
}

// ---------------- K2: fused reduce(72 chunks) + bias + relu + 1x1 convs + box decode
// out: [0,2048) pos_conf | [2048,4096) neg_conf |
//      [4096,12288) pos_offsets[2048][4] | [12288,20480) proposals[2048][4]
__global__ void k_tail(const int* __restrict__ posi, const int* __restrict__ negi,
                       const float* __restrict__ pos_ancs,
                       const float* __restrict__ bh,
                       const float* __restrict__ Wc, const float* __restrict__ bc,
                       const float* __restrict__ Wr, const float* __restrict__ br,
                       float* __restrict__ out)
{
    int e = blockIdx.x * blockDim.x + threadIdx.x;
    if (e >= NENT) return;
    int flat = (e < NPOS) ? posi[e] : negi[e - NPOS];
    int anc = flat % NANC;

    float h[HID2];
#pragma unroll
    for (int i = 0; i < HID2; i++) h[i] = 0.f;
#pragma unroll 4
    for (int c = 0; c < NCHUNKS; c++) {
        const float2* p = (const float2*)(d_part + (size_t)c * NENT * HID2 + e * HID2);
#pragma unroll
        for (int q = 0; q < 5; q++) {
            float2 v = p[q];
            h[2 * q] += v.x; h[2 * q + 1] += v.y;
        }
    }
#pragma unroll
    for (int i = 0; i < HID; i++) h[i] = fmaxf(h[i] + bh[i], 0.f);

    float conf = bc[anc];
#pragma unroll
    for (int i = 0; i < HID; i++) conf = fmaf(Wc[anc * HID + i], h[i], conf);
    out[e] = conf;

    if (e < NPOS) {
        float off[4];
#pragma unroll
        for (int j = 0; j < 4; j++) {
            int r = anc * 4 + j;
            float s = br[r];
#pragma unroll
            for (int i = 0; i < HID; i++) s = fmaf(Wr[r * HID + i], h[i], s);
            off[j] = s;
            out[4096 + e * 4 + j] = s;
        }
        const float* pa = pos_ancs + e * 4;
        float cx = (pa[0] + pa[2]) * 0.5f;
        float cy = (pa[1] + pa[3]) * 0.5f;
        float w  = pa[2] - pa[0];
        float hh = pa[3] - pa[1];
        float ncx = fmaf(off[0], w,  cx);
        float ncy = fmaf(off[1], hh, cy);
        float nw  = w  * expf(off[2]);
        float nh  = hh * expf(off[3]);
        out[12288 + e * 4 + 0] = ncx - nw * 0.5f;
        out[12288 + e * 4 + 1] = ncy - nh * 0.5f;
        out[12288 + e * 4 + 2] = ncx + nw * 0.5f;
        out[12288 + e * 4 + 3] = ncy + nh * 0.5f;
    }
}

extern "C" void kernel_launch(void* const* d_in, const int* in_sizes, int n_in,
                              void* d_out, int out_size) {
    const float* F   = (const float*)d_in[0];
    const int*   pi  = (const int*)  d_in[1];
    const int*   ni  = (const int*)  d_in[2];
    const float* pa  = (const float*)d_in[3];
    const float* Wh  = (const float*)d_in[4];
    const float* bh  = (const float*)d_in[5];
    const float* Wc  = (const float*)d_in[6];
    const float* bc  = (const float*)d_in[7];
    const float* Wr  = (const float*)d_in[8];
    const float* br  = (const float*)d_in[9];
    float* out = (float*)d_out;

    cudaFuncSetAttribute(k_conv, cudaFuncAttributeMaxDynamicSharedMemorySize, SMEM_BYTES);
    k_prep<<<(CIN * 50 + 255) / 256, 256>>>(Wh);
    dim3 grid(B_, NGRP);
    k_conv<<<grid, 256, SMEM_BYTES>>>(F, pi, ni);
    k_tail<<<(NENT + 127) / 128, 128>>>(pi, ni, pa, bh, Wc, bc, Wr, br, out);
}

// round 17
// speedup vs baseline: 1.2841x; 1.2841x over previous
#include <cuda_runtime.h>
#include <math.h>

#define B_      32
#define CIN     2048
#define NPIX    625        // 25*25
#define NANC    9
#define HID     9
#define HID2    10         // padded (h=9 zero) -> 5 f32x2 pairs
#define NPOS    2048
#define NENT    4096
#define MAXINST 256
#define NPER    5          // instances per thread
#define WIN     160        // instances per sweep (32 lanes * 5)
#define NGRP    9          // grid.y -> 288 blocks = single wave at 2/SM
#define NCHUNKS (NGRP * 8) // 72 partial chunks

typedef unsigned long long ull;

// Scratch (device globals: no allocation allowed)
__device__ float d_part[(size_t)NCHUNKS * NENT * HID2];  // ~11.8 MB, write-once
__device__ ull   d_Wp[CIN * 50];   // [c][h2][10 taps] f32x2 pairs (tap 9 = pad)

__device__ __forceinline__ ull pk2(float lo, float hi) {
    ull r; asm("mov.b64 %0, {%1, %2};" : "=l"(r) : "f"(lo), "f"(hi)); return r;
}
__device__ __forceinline__ void fma2(ull& d, ull a, ull b) {
    asm("fma.rn.f32x2 %0, %1, %2, %3;" : "=l"(d) : "l"(a), "l"(b), "l"(d));
}
__device__ __forceinline__ void cpa16(unsigned s, const void* g) {
    asm volatile("cp.async.cg.shared.global [%0], [%1], 16;" :: "r"(s), "l"(g));
}
__device__ __forceinline__ void cpa4(unsigned s, const void* g) {
    asm volatile("cp.async.ca.shared.global [%0], [%1], 4;" :: "r"(s), "l"(g));
}
#define CPA_COMMIT() asm volatile("cp.async.commit_group;")
#define CPA_WAIT0()  asm volatile("cp.async.wait_group 0;" ::: "memory")
#define CPA_WAIT1()  asm volatile("cp.async.wait_group 1;" ::: "memory")

// smem layout (bytes): per-warp private slabs
// F: warp w at [w*10000, +2*5000) ; W: 80000 + w*1600, 2*800
#define FW_STRIDE 10000
#define FBUFW     5000
#define OFF_W     80000
#define WW_STRIDE 1600
#define WBUFW     800
#define OFF_UB    (OFF_W + 8 * WW_STRIDE)   // 92800
#define OFF_UE    (OFF_UB + MAXINST * 2)
#define OFF_SB    (OFF_UE + MAXINST * 2)
#define OFF_SE    (OFF_SB + MAXINST * 2)
#define OFF_BCNT  (OFF_SE + MAXINST * 2)
#define OFF_BOFF  (OFF_BCNT + 128)
#define OFF_CNT   (OFF_BOFF + 128)
#define SMEM_BYTES (OFF_CNT + 16)           // ~95.1 KB -> 2 blocks/SM

// ---------------- K0: pack weights [h][c][3][3] -> [c][h2][10] f32x2 pairs
__global__ void k_prep(const float* __restrict__ Wh) {
    int idx = blockIdx.x * blockDim.x + threadIdx.x;
    if (idx >= CIN * 50) return;
    int c = idx / 50, rm = idx % 50, h2 = rm / 10, t = rm % 10;
    float lo = 0.f, hi = 0.f;
    if (t < 9) {
        lo = Wh[((size_t)(2 * h2) * CIN + c) * 9 + t];
        if (2 * h2 + 1 < HID) hi = Wh[((size_t)(2 * h2 + 1) * CIN + c) * 9 + t];
    }
    ((float2*)d_Wp)[idx] = make_float2(lo, hi);
}

// ---------------- K1: sparse 3x3 conv partials.
// grid = (32 images, 9 channel-groups); block = 256 threads (8 warps).
// Each warp runs an AUTONOMOUS channel stream: private double-buffered smem,
// per-warp cp.async pipeline (depth 2), NO block barriers in the main loop.
__global__ void __launch_bounds__(256, 2) k_conv(
    const float* __restrict__ F,
    const int* __restrict__ posi,
    const int* __restrict__ negi)
{
    extern __shared__ char smem[];
    unsigned short* s_ub = (unsigned short*)(smem + OFF_UB);
    unsigned short* s_ue = (unsigned short*)(smem + OFF_UE);
    unsigned short* s_sb = (unsigned short*)(smem + OFF_SB);
    unsigned short* s_se = (unsigned short*)(smem + OFF_SE);
    int* s_bcnt = (int*)(smem + OFF_BCNT);
    int* s_boff = (int*)(smem + OFF_BOFF);
    int* s_cnt  = (int*)(smem + OFF_CNT);
    const unsigned sm0 = (unsigned)__cvta_generic_to_shared(smem);

    const int b    = blockIdx.x;
    const int g    = blockIdx.y;
    const int c0   = (g < 2) ? g * 240 : 480 + (g - 2) * 224;   // 2x15+7x14 stages
    const int nst  = (g < 2) ? 15 : 14;                          // of 16 ch (2/warp)
    const int tid  = threadIdx.x;
    const int lane = tid & 31;
    const int wid  = tid >> 5;

    if (tid == 0) *s_cnt = 0;
    if (tid < 32) s_bcnt[tid] = 0;
    __syncthreads();

    // gather entries of image b; key = conv base offset (y-1)*25+(x-1), stored +64
    for (int e = tid; e < NENT; e += 256) {
        int flat = (e < NPOS) ? posi[e] : negi[e - NPOS];
        if (flat / (NPIX * NANC) == b) {
            int s = atomicAdd(s_cnt, 1);
            if (s < MAXINST) {
                int rem = flat % (NPIX * NANC);
                int pix = rem / NANC;
                int y = pix / 25, x = pix - y * 25;
                s_ub[s] = (unsigned short)((y - 1) * 25 + (x - 1) + 64);
                s_ue[s] = (unsigned short)e;
            }
        }
    }
    __syncthreads();
    const int ninst = min(*s_cnt, MAXINST);
    if (ninst == 0) return;   // block-uniform

    // counting sort by (base mod 32) -> near-conflict-free patch LDS
    for (int i = tid; i < ninst; i += 256) atomicAdd(&s_bcnt[s_ub[i] & 31], 1);
    __syncthreads();
    if (wid == 0) {
        int v = s_bcnt[lane];
#pragma unroll
        for (int d = 1; d < 32; d <<= 1) {
            int t = __shfl_up_sync(0xffffffffu, v, d);
            if (lane >= d) v += t;
        }
        s_boff[lane] = v - s_bcnt[lane];
    }
    __syncthreads();
    for (int i = tid; i < ninst; i += 256) {
        int bs = s_ub[i];
        int p = atomicAdd(&s_boff[bs & 31], 1);
        s_sb[p] = (unsigned short)bs;
        s_se[p] = s_ue[i];
    }
    __syncthreads();
    // ---- from here on: warps fully independent (s_sb/s_se read-only) ----

    // per-warp cp.async stage issue: 2 planes (1250 x 4B) + weights (100 x 16B)
    auto stage_issue = [&](int s) {
        const int cb = c0 + s * 16 + wid * 2;
        const float* gF = F + ((size_t)b * CIN + cb) * NPIX;
        const unsigned dF = sm0 + wid * FW_STRIDE + (s & 1) * FBUFW;
        for (int i = lane; i < 2 * NPIX; i += 32) cpa4(dF + i * 4, gF + i);
        const char* gW = (const char*)(d_Wp + (size_t)cb * 50);
        const unsigned dW = sm0 + OFF_W + wid * WW_STRIDE + (s & 1) * WBUFW;
        for (int i = lane; i < WBUFW / 16; i += 32) cpa16(dW + i * 16, gW + i * 16);
        CPA_COMMIT();
    };

    for (int w0 = 0; w0 < ninst; w0 += WIN) {
        // per-thread instances: base + 9-bit border mask (invalid -> mk=0)
        int      ibase[NPER];
        unsigned mk[NPER];
#pragma unroll
        for (int j = 0; j < NPER; j++) {
            int r = w0 + lane * NPER + j;
            if (r < ninst) {
                int base = (int)s_sb[r] - 64;
                ibase[j] = base;
                int v = base + 26;          // = 25*y + x
                int y = v / 25, x = v - 25 * y;
                unsigned m = 0;
#pragma unroll
                for (int t = 0; t < 9; t++) {
                    int dy = t / 3, dx = t - dy * 3;
                    if ((unsigned)(y - 1 + dy) < 25u && (unsigned)(x - 1 + dx) < 25u)
                        m |= 1u << t;
                }
                mk[j] = m;
            } else { ibase[j] = 0; mk[j] = 0u; }
        }

        ull acc[NPER][5];
#pragma unroll
        for (int j = 0; j < NPER; j++)
#pragma unroll
            for (int h2 = 0; h2 < 5; h2++) acc[j][h2] = 0ull;

        stage_issue(0);
        stage_issue(1);
        for (int s = 0; s < nst; s++) {
            if (s == nst - 1) { CPA_WAIT0(); } else { CPA_WAIT1(); }
            // stage s copies complete (warp-local pipeline)
            const int buf = s & 1;
            const float* sFb = (const float*)(smem + wid * FW_STRIDE + buf * FBUFW);
            const ull*   sWb = (const ull*)(smem + OFF_W + wid * WW_STRIDE + buf * WBUFW);
#pragma unroll
            for (int kk = 0; kk < 2; kk++) {
                const float* fpl = sFb + kk * NPIX;
                const ull*   wk  = sWb + kk * 50;
                // tap pairs (0,1)(2,3)(4,5)(6,7): LDS.128 weight loads
#pragma unroll
                for (int tp = 0; tp < 4; tp++) {
                    const int t0 = 2 * tp, t1 = t0 + 1;
                    const int o0 = (t0 / 3) * 25 + t0 % 3;
                    const int o1 = (t1 / 3) * 25 + t1 % 3;
                    ulonglong2 w01[5];
#pragma unroll
                    for (int h2 = 0; h2 < 5; h2++)
                        w01[h2] = *(const ulonglong2*)(wk + h2 * 10 + t0);
#pragma unroll
                    for (int j = 0; j < NPER; j++) {
                        float v0 = 0.f, v1 = 0.f;
                        if (mk[j] >> t0 & 1u) v0 = fpl[ibase[j] + o0];
                        if (mk[j] >> t1 & 1u) v1 = fpl[ibase[j] + o1];
                        ull p0 = pk2(v0, v0), p1 = pk2(v1, v1);
#pragma unroll
                        for (int h2 = 0; h2 < 5; h2++) {
                            fma2(acc[j][h2], p0, w01[h2].x);
                            fma2(acc[j][h2], p1, w01[h2].y);
                        }
                    }
                }
                // tap 8
                {
                    ull w8[5];
#pragma unroll
                    for (int h2 = 0; h2 < 5; h2++) w8[h2] = wk[h2 * 10 + 8];
#pragma unroll
                    for (int j = 0; j < NPER; j++) {
                        float v = 0.f;
                        if (mk[j] >> 8 & 1u) v = fpl[ibase[j] + 52];
                        ull p = pk2(v, v);
#pragma unroll
                        for (int h2 = 0; h2 < 5; h2++) fma2(acc[j][h2], p, w8[h2]);
                    }
                }
            }
            if (s + 2 < nst) stage_issue(s + 2);   // program-ordered after compute
        }

        // write-once partials: chunk = (g, warp)
        const int chunk = g * 8 + wid;
        float* cp = d_part + (size_t)chunk * NENT * HID2;
#pragma unroll
        for (int j = 0; j < NPER; j++) {
            int r = w0 + lane * NPER + j;
            if (r >= ninst) continue;
            int e = s_se[r];
            ull* dst = (ull*)(cp + e * HID2);
#pragma unroll
            for (int h2 = 0; h2 < 5; h2++) dst[h2] = acc[j][h2];
        }
        // no barrier: all buffers are warp-private
    }
}

// ---------------- K2: fused reduce(72 chunks) + bias + relu + 1x1 convs + box decode
// out: [0,2048) pos_conf | [2048,4096) neg_conf |
//      [4096,12288) pos_offsets[2048][4] | [12288,20480) proposals[2048][4]
__global__ void k_tail(const int* __restrict__ posi, const int* __restrict__ negi,
                       const float* __restrict__ pos_ancs,
                       const float* __restrict__ bh,
                       const float* __restrict__ Wc, const float* __restrict__ bc,
                       const float* __restrict__ Wr, const float* __restrict__ br,
                       float* __restrict__ out)
{
    int e = blockIdx.x * blockDim.x + threadIdx.x;
    if (e >= NENT) return;
    int flat = (e < NPOS) ? posi[e] : negi[e - NPOS];
    int anc = flat % NANC;

    float h[HID2];
#pragma unroll
    for (int i = 0; i < HID2; i++) h[i] = 0.f;
#pragma unroll 4
    for (int c = 0; c < NCHUNKS; c++) {
        const float2* p = (const float2*)(d_part + (size_t)c * NENT * HID2 + e * HID2);
#pragma unroll
        for (int q = 0; q < 5; q++) {
            float2 v = p[q];
            h[2 * q] += v.x; h[2 * q + 1] += v.y;
        }
    }
#pragma unroll
    for (int i = 0; i < HID; i++) h[i] = fmaxf(h[i] + bh[i], 0.f);

    float conf = bc[anc];
#pragma unroll
    for (int i = 0; i < HID; i++) conf = fmaf(Wc[anc * HID + i], h[i], conf);
    out[e] = conf;

    if (e < NPOS) {
        float off[4];
#pragma unroll
        for (int j = 0; j < 4; j++) {
            int r = anc * 4 + j;
            float s = br[r];
#pragma unroll
            for (int i = 0; i < HID; i++) s = fmaf(Wr[r * HID + i], h[i], s);
            off[j] = s;
            out[4096 + e * 4 + j] = s;
        }
        const float* pa = pos_ancs + e * 4;
        float cx = (pa[0] + pa[2]) * 0.5f;
        float cy = (pa[1] + pa[3]) * 0.5f;
        float w  = pa[2] - pa[0];
        float hh = pa[3] - pa[1];
        float ncx = fmaf(off[0], w,  cx);
        float ncy = fmaf(off[1], hh, cy);
        float nw  = w  * expf(off[2]);
        float nh  = hh * expf(off[3]);
        out[12288 + e * 4 + 0] = ncx - nw * 0.5f;
        out[12288 + e * 4 + 1] = ncy - nh * 0.5f;
        out[12288 + e * 4 + 2] = ncx + nw * 0.5f;
        out[12288 + e * 4 + 3] = ncy + nh * 0.5f;
    }
}

extern "C" void kernel_launch(void* const* d_in, const int* in_sizes, int n_in,
                              void* d_out, int out_size) {
    const float* F   = (const float*)d_in[0];
    const int*   pi  = (const int*)  d_in[1];
    const int*   ni  = (const int*)  d_in[2];
    const float* pa  = (const float*)d_in[3];
    const float* Wh  = (const float*)d_in[4];
    const float* bh  = (const float*)d_in[5];
    const float* Wc  = (const float*)d_in[6];
    const float* bc  = (const float*)d_in[7];
    const float* Wr  = (const float*)d_in[8];
    const float* br  = (const float*)d_in[9];
    float* out = (float*)d_out;

    cudaFuncSetAttribute(k_conv, cudaFuncAttributeMaxDynamicSharedMemorySize, SMEM_BYTES);
    k_prep<<<(CIN * 50 + 255) / 256, 256>>>(Wh);
    dim3 grid(B_, NGRP);
    k_conv<<<grid, 256, SMEM_BYTES>>>(F, pi, ni);
    k_tail<<<(NENT + 127) / 128, 128>>>(pi, ni, pa, bh, Wc, bc, Wr, br, out);
}